// round 15
// baseline (speedup 1.0000x reference)
#include <cuda_runtime.h>

// ---------------------------------------------------------------------------
// PaiNN message passing:
//   s_norm = RMSNorm(s); phi = W2 @ silu(W1 @ s_norm + b1) + b2   [N,384]
//   filt   = phi[j] * rbf                                          [E,384]
//   out_s[i] += SCALE * filt[:,0:128]
//   out_v[i,k] += SCALE * (v[j,k]*filt[:,128:256] + ev[e,k]*filt[:,256:384])
//   out_s seeded with s, out_v with v.
// ---------------------------------------------------------------------------

#define CDIM 128
#define SCALE_F 0.0625f
#define EPS_F 1.1920929e-07f
#define TM 64            // nodes per CTA in the phi kernel
#define SROW 132         // padded shared row stride (floats)
#define MAXN 12288

__device__ float g_phi[(size_t)MAXN * 3 * CDIM];   // 18.9 MB static scratch
__device__ int   g_idx_is64;                       // edge_index dtype flag

// ---------------------------------------------------------------------------
// Kernel 0: seed output with residual (out = [s | v]); reset dtype flag.
// ---------------------------------------------------------------------------
__global__ void init_out_kernel(const float4* __restrict__ s4,
                                const float4* __restrict__ v4,
                                float4* __restrict__ out4,
                                int n_s4, int n_total4) {
    int idx = blockIdx.x * blockDim.x + threadIdx.x;
    if (idx == 0) g_idx_is64 = 1;
    if (idx >= n_total4) return;
    out4[idx] = (idx < n_s4) ? s4[idx] : v4[idx - n_s4];
}

// ---------------------------------------------------------------------------
// Kernel 0b: detect edge_index dtype. Reads only the FIRST E 8-byte words,
// which is in-bounds whether the buffer holds 2E int32 or 2E int64.
// int64 data: every word is a valid node id in [0,N).
// int32 data: word = lo + hi*2^32 with hi a node id; any hi!=0 -> >= 2^32.
// ---------------------------------------------------------------------------
__global__ void detect_idx_kernel(const long long* __restrict__ ei,
                                  int N, int E) {
    int stride = gridDim.x * blockDim.x;
    for (int t = blockIdx.x * blockDim.x + threadIdx.x; t < E; t += stride) {
        long long vv = ei[t];
        if (vv < 0 || vv >= (long long)N) { g_idx_is64 = 0; return; }
    }
}

// ---------------------------------------------------------------------------
// Kernel 1: per-node RMSNorm + MLP -> g_phi [N,384]
// 256 threads, TM=64 nodes/CTA. Register-tiled fp32 GEMM (4x8 microtile).
// ---------------------------------------------------------------------------
__global__ void __launch_bounds__(256)
node_phi_kernel(const float* __restrict__ s,
                const float* __restrict__ w1, const float* __restrict__ b1,
                const float* __restrict__ w2, const float* __restrict__ b2,
                const float* __restrict__ rmsw, int N) {
    extern __shared__ float smem[];
    float* sS = smem;                 // TM * SROW
    float* sW = smem + TM * SROW;     // CDIM * SROW

    const int tid = threadIdx.x;
    const int n0 = blockIdx.x * TM;

    // ---- load s tile (coalesced float4) ----
    const float4* S4 = (const float4*)s;
    for (int t = tid; t < TM * (CDIM / 4); t += 256) {
        int m = t >> 5, cq = t & 31;
        float4 val = make_float4(0.f, 0.f, 0.f, 0.f);
        if (n0 + m < N) val = S4[(size_t)(n0 + m) * (CDIM / 4) + cq];
        *(float4*)&sS[m * SROW + cq * 4] = val;
    }
    __syncthreads();

    // ---- RMSNorm: 4 threads per row ----
    {
        int m = tid >> 2, part = tid & 3;
        float ss = 0.f;
        #pragma unroll
        for (int q = 0; q < 8; q++) {
            float4 a = *(float4*)&sS[m * SROW + part * 32 + q * 4];
            ss += a.x * a.x + a.y * a.y + a.z * a.z + a.w * a.w;
        }
        ss += __shfl_xor_sync(0xffffffffu, ss, 1);
        ss += __shfl_xor_sync(0xffffffffu, ss, 2);
        float sc = rsqrtf(ss * (1.0f / CDIM) + EPS_F);
        #pragma unroll
        for (int q = 0; q < 8; q++) {
            int c = part * 32 + q * 4;
            float4 a = *(float4*)&sS[m * SROW + c];
            float4 w = *(const float4*)&rmsw[c];
            a.x *= sc * w.x; a.y *= sc * w.y; a.z *= sc * w.z; a.w *= sc * w.w;
            *(float4*)&sS[m * SROW + c] = a;
        }
    }

    // ---- stage W1 into shared ----
    const float4* W1_4 = (const float4*)w1;
    for (int t = tid; t < CDIM * (CDIM / 4); t += 256) {
        int r = t >> 5, cq = t & 31;
        *(float4*)&sW[r * SROW + cq * 4] = W1_4[r * (CDIM / 4) + cq];
    }
    __syncthreads();

    const int tc = tid & 15;   // 16 col-lanes; d = tc + 16*j
    const int tr = tid >> 4;   // 16 row-groups; m = tr*4 + i

    // ---- Stage 1: H = silu(Snorm @ W1^T + b1) ----
    float acc[4][8];
    #pragma unroll
    for (int i = 0; i < 4; i++)
        #pragma unroll
        for (int j = 0; j < 8; j++) acc[i][j] = 0.f;

    #pragma unroll 4
    for (int c = 0; c < CDIM; c += 4) {
        float4 a[4], b[8];
        #pragma unroll
        for (int i = 0; i < 4; i++) a[i] = *(float4*)&sS[(tr * 4 + i) * SROW + c];
        #pragma unroll
        for (int j = 0; j < 8; j++) b[j] = *(float4*)&sW[(tc + 16 * j) * SROW + c];
        #pragma unroll
        for (int i = 0; i < 4; i++)
            #pragma unroll
            for (int j = 0; j < 8; j++) {
                acc[i][j] = fmaf(a[i].x, b[j].x, acc[i][j]);
                acc[i][j] = fmaf(a[i].y, b[j].y, acc[i][j]);
                acc[i][j] = fmaf(a[i].z, b[j].z, acc[i][j]);
                acc[i][j] = fmaf(a[i].w, b[j].w, acc[i][j]);
            }
    }
    // bias + silu (in registers)
    #pragma unroll
    for (int j = 0; j < 8; j++) {
        float bb = b1[tc + 16 * j];
        #pragma unroll
        for (int i = 0; i < 4; i++) {
            float x = acc[i][j] + bb;
            acc[i][j] = x / (1.0f + __expf(-x));
        }
    }
    __syncthreads();
    // H overwrites snorm tile
    #pragma unroll
    for (int i = 0; i < 4; i++)
        #pragma unroll
        for (int j = 0; j < 8; j++)
            sS[(tr * 4 + i) * SROW + tc + 16 * j] = acc[i][j];
    __syncthreads();

    // ---- Stage 2: phi_g = H @ W2_g^T + b2_g  for g = 0..2 ----
    for (int g = 0; g < 3; g++) {
        const float4* W2_4 = (const float4*)(w2 + (size_t)g * CDIM * CDIM);
        for (int t = tid; t < CDIM * (CDIM / 4); t += 256) {
            int r = t >> 5, cq = t & 31;
            *(float4*)&sW[r * SROW + cq * 4] = W2_4[r * (CDIM / 4) + cq];
        }
        __syncthreads();

        float pac[4][8];
        #pragma unroll
        for (int i = 0; i < 4; i++)
            #pragma unroll
            for (int j = 0; j < 8; j++) pac[i][j] = 0.f;

        #pragma unroll 4
        for (int c = 0; c < CDIM; c += 4) {
            float4 a[4], b[8];
            #pragma unroll
            for (int i = 0; i < 4; i++) a[i] = *(float4*)&sS[(tr * 4 + i) * SROW + c];
            #pragma unroll
            for (int j = 0; j < 8; j++) b[j] = *(float4*)&sW[(tc + 16 * j) * SROW + c];
            #pragma unroll
            for (int i = 0; i < 4; i++)
                #pragma unroll
                for (int j = 0; j < 8; j++) {
                    pac[i][j] = fmaf(a[i].x, b[j].x, pac[i][j]);
                    pac[i][j] = fmaf(a[i].y, b[j].y, pac[i][j]);
                    pac[i][j] = fmaf(a[i].z, b[j].z, pac[i][j]);
                    pac[i][j] = fmaf(a[i].w, b[j].w, pac[i][j]);
                }
        }
        #pragma unroll
        for (int i = 0; i < 4; i++) {
            int node = n0 + tr * 4 + i;
            if (node < N) {
                float* dst = &g_phi[(size_t)node * (3 * CDIM) + g * CDIM];
                #pragma unroll
                for (int j = 0; j < 8; j++)
                    dst[tc + 16 * j] = pac[i][j] + b2[g * CDIM + tc + 16 * j];
            }
        }
        __syncthreads();
    }
}

// ---------------------------------------------------------------------------
// Kernel 2: edge gather-multiply-scatter. One warp per edge, one float4
// column slice per lane. Vector float4 atomics into d_out (residual-seeded).
// Index dtype resolved via g_idx_is64 (uniform branch).
// ---------------------------------------------------------------------------
__global__ void __launch_bounds__(256)
edge_kernel(const void* __restrict__ ei_raw,
            const float* __restrict__ rbf,
            const float* __restrict__ ev,
            const float* __restrict__ v,
            float* __restrict__ out, int N, int E) {
    const int wid = threadIdx.x >> 5;
    const int lane = threadIdx.x & 31;
    const int e = blockIdx.x * 8 + wid;
    if (e >= E) return;

    int di, sj;
    if (g_idx_is64) {
        const long long* ei = (const long long*)ei_raw;
        di = (int)ei[e];          // destination (segment index)
        sj = (int)ei[E + e];      // source
    } else {
        const int* ei = (const int*)ei_raw;
        di = ei[e];
        sj = ei[E + e];
    }
    // clamp defensively (garbage indices must never fault)
    di = min(max(di, 0), N - 1);
    sj = min(max(sj, 0), N - 1);

    const float4* Phi = (const float4*)g_phi;
    const float4* R4  = (const float4*)rbf;
    const float4* V4  = (const float4*)v;

    const size_t pb = (size_t)sj * 96;
    const size_t rb = (size_t)e * 96;

    float4 p0 = Phi[pb + lane],      r0 = R4[rb + lane];
    float4 p1 = Phi[pb + 32 + lane], r1 = R4[rb + 32 + lane];
    float4 p2 = Phi[pb + 64 + lane], r2 = R4[rb + 64 + lane];

    float4 ms  = make_float4(p0.x * r0.x * SCALE_F, p0.y * r0.y * SCALE_F,
                             p0.z * r0.z * SCALE_F, p0.w * r0.w * SCALE_F);
    float4 mvv = make_float4(p1.x * r1.x * SCALE_F, p1.y * r1.y * SCALE_F,
                             p1.z * r1.z * SCALE_F, p1.w * r1.w * SCALE_F);
    float4 mvs = make_float4(p2.x * r2.x * SCALE_F, p2.y * r2.y * SCALE_F,
                             p2.z * r2.z * SCALE_F, p2.w * r2.w * SCALE_F);

    float4* OutS = (float4*)out;                            // [N,128]
    float4* OutV = (float4*)(out + (size_t)N * CDIM);       // [N,3,128]

    atomicAdd(&OutS[(size_t)di * 32 + lane], ms);

    #pragma unroll
    for (int k = 0; k < 3; k++) {
        float evk = ev[(size_t)e * 3 + k];
        float4 vk = V4[((size_t)sj * 3 + k) * 32 + lane];
        float4 dv = make_float4(fmaf(vk.x, mvv.x, evk * mvs.x),
                                fmaf(vk.y, mvv.y, evk * mvs.y),
                                fmaf(vk.z, mvv.z, evk * mvs.z),
                                fmaf(vk.w, mvv.w, evk * mvs.w));
        atomicAdd(&OutV[((size_t)di * 3 + k) * 32 + lane], dv);
    }
}

// ---------------------------------------------------------------------------
// Launch
// Input order: s, v, edge_index, rbf_filter, edge_vector, w1, b1, w2, b2,
//              rms_w.   Output: [s_out (N*128) | v_out (N*3*128)] fp32.
// ---------------------------------------------------------------------------
extern "C" void kernel_launch(void* const* d_in, const int* in_sizes, int n_in,
                              void* d_out, int out_size) {
    const float* s    = (const float*)d_in[0];
    const float* v    = (const float*)d_in[1];
    const void*  ei   = d_in[2];
    const float* rbf  = (const float*)d_in[3];
    const float* ev   = (const float*)d_in[4];
    const float* w1   = (const float*)d_in[5];
    const float* b1   = (const float*)d_in[6];
    const float* w2   = (const float*)d_in[7];
    const float* b2   = (const float*)d_in[8];
    const float* rmsw = (const float*)d_in[9];

    const int N = in_sizes[0] / CDIM;       // 10000
    const int E = in_sizes[2] / 2;          // 160000
    float* out = (float*)d_out;

    // Kernel 0: out = [s | v]; reset dtype flag to "int64"
    {
        int n_s4 = N * (CDIM / 4);
        int n_total4 = N * CDIM;            // (N*512 floats)/4
        int blocks = (n_total4 + 255) / 256;
        init_out_kernel<<<blocks, 256>>>((const float4*)s, (const float4*)v,
                                         (float4*)out, n_s4, n_total4);
    }

    // Kernel 0b: probe edge_index dtype (reads only first E 8-byte words)
    detect_idx_kernel<<<160, 256>>>((const long long*)ei, N, E);

    // Kernel 1: phi
    {
        size_t smem_bytes = (size_t)(TM + CDIM) * SROW * sizeof(float); // ~99 KB
        cudaFuncSetAttribute(node_phi_kernel,
                             cudaFuncAttributeMaxDynamicSharedMemorySize,
                             (int)smem_bytes);
        int blocks = (N + TM - 1) / TM;
        node_phi_kernel<<<blocks, 256, smem_bytes>>>(s, w1, b1, w2, b2, rmsw, N);
    }

    // Kernel 2: edges
    {
        int blocks = (E + 7) / 8;
        edge_kernel<<<blocks, 256>>>(ei, rbf, ev, v, out, N, E);
    }
}

// round 16
// speedup vs baseline: 1.0023x; 1.0023x over previous
#include <cuda_runtime.h>

// ---------------------------------------------------------------------------
// PaiNN message passing:
//   s_norm = RMSNorm(s); phi = W2 @ silu(W1 @ s_norm + b1) + b2   [N,384]
//   filt   = phi[j] * rbf                                          [E,384]
//   out_s[i] += SCALE * filt[:,0:128]
//   out_v[i,k] += SCALE * (v[j,k]*filt[:,128:256] + ev[e,k]*filt[:,256:384])
//   out_s seeded with s, out_v with v.
// ---------------------------------------------------------------------------

#define CDIM 128
#define SCALE_F 0.0625f
#define EPS_F 1.1920929e-07f
#define TM 64            // nodes per CTA in the phi kernel
#define SROW 132         // padded shared row stride (floats)
#define MAXN 12288

__device__ float g_phi[(size_t)MAXN * 3 * CDIM];   // 18.9 MB static scratch
__device__ int   g_idx_is64;                       // edge_index dtype flag

// ---------------------------------------------------------------------------
// Kernel 0: seed output with residual (out = [s | v]); reset dtype flag.
// ---------------------------------------------------------------------------
__global__ void init_out_kernel(const float4* __restrict__ s4,
                                const float4* __restrict__ v4,
                                float4* __restrict__ out4,
                                int n_s4, int n_total4) {
    int idx = blockIdx.x * blockDim.x + threadIdx.x;
    if (idx == 0) g_idx_is64 = 1;
    if (idx >= n_total4) return;
    out4[idx] = (idx < n_s4) ? s4[idx] : v4[idx - n_s4];
}

// ---------------------------------------------------------------------------
// Kernel 0b: detect edge_index dtype. Reads only the FIRST E 8-byte words,
// which is in-bounds whether the buffer holds 2E int32 or 2E int64.
// int64 data: every word is a valid node id in [0,N).
// int32 data: word = lo + hi*2^32 with hi a node id; any hi!=0 -> >= 2^32.
// ---------------------------------------------------------------------------
__global__ void detect_idx_kernel(const long long* __restrict__ ei,
                                  int N, int E) {
    int stride = gridDim.x * blockDim.x;
    for (int t = blockIdx.x * blockDim.x + threadIdx.x; t < E; t += stride) {
        long long vv = ei[t];
        if (vv < 0 || vv >= (long long)N) { g_idx_is64 = 0; return; }
    }
}

// ---------------------------------------------------------------------------
// Kernel 1: per-node RMSNorm + MLP -> g_phi [N,384]
// 256 threads, TM=64 nodes/CTA. Register-tiled fp32 GEMM (4x8 microtile).
// ---------------------------------------------------------------------------
__global__ void __launch_bounds__(256)
node_phi_kernel(const float* __restrict__ s,
                const float* __restrict__ w1, const float* __restrict__ b1,
                const float* __restrict__ w2, const float* __restrict__ b2,
                const float* __restrict__ rmsw, int N) {
    extern __shared__ float smem[];
    float* sS = smem;                 // TM * SROW
    float* sW = smem + TM * SROW;     // CDIM * SROW

    const int tid = threadIdx.x;
    const int n0 = blockIdx.x * TM;

    // ---- load s tile (coalesced float4) ----
    const float4* S4 = (const float4*)s;
    for (int t = tid; t < TM * (CDIM / 4); t += 256) {
        int m = t >> 5, cq = t & 31;
        float4 val = make_float4(0.f, 0.f, 0.f, 0.f);
        if (n0 + m < N) val = S4[(size_t)(n0 + m) * (CDIM / 4) + cq];
        *(float4*)&sS[m * SROW + cq * 4] = val;
    }
    __syncthreads();

    // ---- RMSNorm: 4 threads per row ----
    {
        int m = tid >> 2, part = tid & 3;
        float ss = 0.f;
        #pragma unroll
        for (int q = 0; q < 8; q++) {
            float4 a = *(float4*)&sS[m * SROW + part * 32 + q * 4];
            ss += a.x * a.x + a.y * a.y + a.z * a.z + a.w * a.w;
        }
        ss += __shfl_xor_sync(0xffffffffu, ss, 1);
        ss += __shfl_xor_sync(0xffffffffu, ss, 2);
        float sc = rsqrtf(ss * (1.0f / CDIM) + EPS_F);
        #pragma unroll
        for (int q = 0; q < 8; q++) {
            int c = part * 32 + q * 4;
            float4 a = *(float4*)&sS[m * SROW + c];
            float4 w = *(const float4*)&rmsw[c];
            a.x *= sc * w.x; a.y *= sc * w.y; a.z *= sc * w.z; a.w *= sc * w.w;
            *(float4*)&sS[m * SROW + c] = a;
        }
    }

    // ---- stage W1 into shared ----
    const float4* W1_4 = (const float4*)w1;
    for (int t = tid; t < CDIM * (CDIM / 4); t += 256) {
        int r = t >> 5, cq = t & 31;
        *(float4*)&sW[r * SROW + cq * 4] = W1_4[r * (CDIM / 4) + cq];
    }
    __syncthreads();

    const int tc = tid & 15;   // 16 col-lanes; d = tc + 16*j
    const int tr = tid >> 4;   // 16 row-groups; m = tr*4 + i

    // ---- Stage 1: H = silu(Snorm @ W1^T + b1) ----
    float acc[4][8];
    #pragma unroll
    for (int i = 0; i < 4; i++)
        #pragma unroll
        for (int j = 0; j < 8; j++) acc[i][j] = 0.f;

    #pragma unroll 4
    for (int c = 0; c < CDIM; c += 4) {
        float4 a[4], b[8];
        #pragma unroll
        for (int i = 0; i < 4; i++) a[i] = *(float4*)&sS[(tr * 4 + i) * SROW + c];
        #pragma unroll
        for (int j = 0; j < 8; j++) b[j] = *(float4*)&sW[(tc + 16 * j) * SROW + c];
        #pragma unroll
        for (int i = 0; i < 4; i++)
            #pragma unroll
            for (int j = 0; j < 8; j++) {
                acc[i][j] = fmaf(a[i].x, b[j].x, acc[i][j]);
                acc[i][j] = fmaf(a[i].y, b[j].y, acc[i][j]);
                acc[i][j] = fmaf(a[i].z, b[j].z, acc[i][j]);
                acc[i][j] = fmaf(a[i].w, b[j].w, acc[i][j]);
            }
    }
    // bias + silu (in registers)
    #pragma unroll
    for (int j = 0; j < 8; j++) {
        float bb = b1[tc + 16 * j];
        #pragma unroll
        for (int i = 0; i < 4; i++) {
            float x = acc[i][j] + bb;
            acc[i][j] = x / (1.0f + __expf(-x));
        }
    }
    __syncthreads();
    // H overwrites snorm tile
    #pragma unroll
    for (int i = 0; i < 4; i++)
        #pragma unroll
        for (int j = 0; j < 8; j++)
            sS[(tr * 4 + i) * SROW + tc + 16 * j] = acc[i][j];
    __syncthreads();

    // ---- Stage 2: phi_g = H @ W2_g^T + b2_g  for g = 0..2 ----
    for (int g = 0; g < 3; g++) {
        const float4* W2_4 = (const float4*)(w2 + (size_t)g * CDIM * CDIM);
        for (int t = tid; t < CDIM * (CDIM / 4); t += 256) {
            int r = t >> 5, cq = t & 31;
            *(float4*)&sW[r * SROW + cq * 4] = W2_4[r * (CDIM / 4) + cq];
        }
        __syncthreads();

        float pac[4][8];
        #pragma unroll
        for (int i = 0; i < 4; i++)
            #pragma unroll
            for (int j = 0; j < 8; j++) pac[i][j] = 0.f;

        #pragma unroll 4
        for (int c = 0; c < CDIM; c += 4) {
            float4 a[4], b[8];
            #pragma unroll
            for (int i = 0; i < 4; i++) a[i] = *(float4*)&sS[(tr * 4 + i) * SROW + c];
            #pragma unroll
            for (int j = 0; j < 8; j++) b[j] = *(float4*)&sW[(tc + 16 * j) * SROW + c];
            #pragma unroll
            for (int i = 0; i < 4; i++)
                #pragma unroll
                for (int j = 0; j < 8; j++) {
                    pac[i][j] = fmaf(a[i].x, b[j].x, pac[i][j]);
                    pac[i][j] = fmaf(a[i].y, b[j].y, pac[i][j]);
                    pac[i][j] = fmaf(a[i].z, b[j].z, pac[i][j]);
                    pac[i][j] = fmaf(a[i].w, b[j].w, pac[i][j]);
                }
        }
        #pragma unroll
        for (int i = 0; i < 4; i++) {
            int node = n0 + tr * 4 + i;
            if (node < N) {
                float* dst = &g_phi[(size_t)node * (3 * CDIM) + g * CDIM];
                #pragma unroll
                for (int j = 0; j < 8; j++)
                    dst[tc + 16 * j] = pac[i][j] + b2[g * CDIM + tc + 16 * j];
            }
        }
        __syncthreads();
    }
}

// ---------------------------------------------------------------------------
// Kernel 2: edge gather-multiply-scatter. One warp per edge, one float4
// column slice per lane. Vector float4 atomics into d_out (residual-seeded).
// Index dtype resolved via g_idx_is64 (uniform branch).
// ---------------------------------------------------------------------------
__global__ void __launch_bounds__(256)
edge_kernel(const void* __restrict__ ei_raw,
            const float* __restrict__ rbf,
            const float* __restrict__ ev,
            const float* __restrict__ v,
            float* __restrict__ out, int N, int E) {
    const int wid = threadIdx.x >> 5;
    const int lane = threadIdx.x & 31;
    const int e = blockIdx.x * 8 + wid;
    if (e >= E) return;

    int di, sj;
    if (g_idx_is64) {
        const long long* ei = (const long long*)ei_raw;
        di = (int)ei[e];          // destination (segment index)
        sj = (int)ei[E + e];      // source
    } else {
        const int* ei = (const int*)ei_raw;
        di = ei[e];
        sj = ei[E + e];
    }
    // clamp defensively (garbage indices must never fault)
    di = min(max(di, 0), N - 1);
    sj = min(max(sj, 0), N - 1);

    const float4* Phi = (const float4*)g_phi;
    const float4* R4  = (const float4*)rbf;
    const float4* V4  = (const float4*)v;

    const size_t pb = (size_t)sj * 96;
    const size_t rb = (size_t)e * 96;

    float4 p0 = Phi[pb + lane],      r0 = R4[rb + lane];
    float4 p1 = Phi[pb + 32 + lane], r1 = R4[rb + 32 + lane];
    float4 p2 = Phi[pb + 64 + lane], r2 = R4[rb + 64 + lane];

    float4 ms  = make_float4(p0.x * r0.x * SCALE_F, p0.y * r0.y * SCALE_F,
                             p0.z * r0.z * SCALE_F, p0.w * r0.w * SCALE_F);
    float4 mvv = make_float4(p1.x * r1.x * SCALE_F, p1.y * r1.y * SCALE_F,
                             p1.z * r1.z * SCALE_F, p1.w * r1.w * SCALE_F);
    float4 mvs = make_float4(p2.x * r2.x * SCALE_F, p2.y * r2.y * SCALE_F,
                             p2.z * r2.z * SCALE_F, p2.w * r2.w * SCALE_F);

    float4* OutS = (float4*)out;                            // [N,128]
    float4* OutV = (float4*)(out + (size_t)N * CDIM);       // [N,3,128]

    atomicAdd(&OutS[(size_t)di * 32 + lane], ms);

    #pragma unroll
    for (int k = 0; k < 3; k++) {
        float evk = ev[(size_t)e * 3 + k];
        float4 vk = V4[((size_t)sj * 3 + k) * 32 + lane];
        float4 dv = make_float4(fmaf(vk.x, mvv.x, evk * mvs.x),
                                fmaf(vk.y, mvv.y, evk * mvs.y),
                                fmaf(vk.z, mvv.z, evk * mvs.z),
                                fmaf(vk.w, mvv.w, evk * mvs.w));
        atomicAdd(&OutV[((size_t)di * 3 + k) * 32 + lane], dv);
    }
}

// ---------------------------------------------------------------------------
// Launch
// Input order: s, v, edge_index, rbf_filter, edge_vector, w1, b1, w2, b2,
//              rms_w.   Output: [s_out (N*128) | v_out (N*3*128)] fp32.
// ---------------------------------------------------------------------------
extern "C" void kernel_launch(void* const* d_in, const int* in_sizes, int n_in,
                              void* d_out, int out_size) {
    const float* s    = (const float*)d_in[0];
    const float* v    = (const float*)d_in[1];
    const void*  ei   = d_in[2];
    const float* rbf  = (const float*)d_in[3];
    const float* ev   = (const float*)d_in[4];
    const float* w1   = (const float*)d_in[5];
    const float* b1   = (const float*)d_in[6];
    const float* w2   = (const float*)d_in[7];
    const float* b2   = (const float*)d_in[8];
    const float* rmsw = (const float*)d_in[9];

    const int N = in_sizes[0] / CDIM;       // 10000
    const int E = in_sizes[2] / 2;          // 160000
    float* out = (float*)d_out;

    // Kernel 0: out = [s | v]; reset dtype flag to "int64"
    {
        int n_s4 = N * (CDIM / 4);
        int n_total4 = N * CDIM;            // (N*512 floats)/4
        int blocks = (n_total4 + 255) / 256;
        init_out_kernel<<<blocks, 256>>>((const float4*)s, (const float4*)v,
                                         (float4*)out, n_s4, n_total4);
    }

    // Kernel 0b: probe edge_index dtype (reads only first E 8-byte words)
    detect_idx_kernel<<<160, 256>>>((const long long*)ei, N, E);

    // Kernel 1: phi
    {
        size_t smem_bytes = (size_t)(TM + CDIM) * SROW * sizeof(float); // ~99 KB
        cudaFuncSetAttribute(node_phi_kernel,
                             cudaFuncAttributeMaxDynamicSharedMemorySize,
                             (int)smem_bytes);
        int blocks = (N + TM - 1) / TM;
        node_phi_kernel<<<blocks, 256, smem_bytes>>>(s, w1, b1, w2, b2, rmsw, N);
    }

    // Kernel 2: edges
    {
        int blocks = (E + 7) / 8;
        edge_kernel<<<blocks, 256>>>(ei, rbf, ev, v, out, N, E);
    }
}

// round 17
// speedup vs baseline: 1.0064x; 1.0042x over previous
#include <cuda_runtime.h>

// ---------------------------------------------------------------------------
// PaiNN message passing:
//   s_norm = RMSNorm(s); phi = W2 @ silu(W1 @ s_norm + b1) + b2   [N,384]
//   filt   = phi[j] * rbf                                          [E,384]
//   out_s[i] += SCALE * filt[:,0:128]
//   out_v[i,k] += SCALE * (v[j,k]*filt[:,128:256] + ev[e,k]*filt[:,256:384])
//   out_s seeded with s, out_v with v.
// ---------------------------------------------------------------------------

#define CDIM 128
#define SCALE_F 0.0625f
#define EPS_F 1.1920929e-07f
#define TM 64            // nodes per CTA in the phi kernel
#define SROW 132         // padded shared row stride (floats); 132*4B % 16 == 0
#define MAXN 12288

__device__ float g_phi[(size_t)MAXN * 3 * CDIM];   // 18.9 MB static scratch
__device__ int   g_idx_is64;                       // edge_index dtype flag

// ---- packed f32x2 FMA (sm_100+; PTX-only, ptxas never auto-fuses) ----------
__device__ __forceinline__ unsigned long long ffma2(unsigned long long a,
                                                    unsigned long long b,
                                                    unsigned long long c) {
    unsigned long long d;
    asm("fma.rn.f32x2 %0, %1, %2, %3;" : "=l"(d) : "l"(a), "l"(b), "l"(c));
    return d;
}
// 16B shared load straight into two b64 regs (f32x2 operand form, no repack)
__device__ __forceinline__ void lds_v2u64(unsigned long long& a,
                                          unsigned long long& b,
                                          const float* p) {
    unsigned int addr = (unsigned int)__cvta_generic_to_shared(p);
    asm volatile("ld.shared.v2.b64 {%0, %1}, [%2];" : "=l"(a), "=l"(b) : "r"(addr));
}
__device__ __forceinline__ float unpack_sum(unsigned long long v) {
    float lo, hi;
    asm("mov.b64 {%0, %1}, %2;" : "=f"(lo), "=f"(hi) : "l"(v));
    return lo + hi;
}

// ---------------------------------------------------------------------------
// Kernel 0: seed output with residual (out = [s | v]); reset dtype flag.
// ---------------------------------------------------------------------------
__global__ void init_out_kernel(const float4* __restrict__ s4,
                                const float4* __restrict__ v4,
                                float4* __restrict__ out4,
                                int n_s4, int n_total4) {
    int idx = blockIdx.x * blockDim.x + threadIdx.x;
    if (idx == 0) g_idx_is64 = 1;
    if (idx >= n_total4) return;
    out4[idx] = (idx < n_s4) ? s4[idx] : v4[idx - n_s4];
}

// ---------------------------------------------------------------------------
// Kernel 0b: detect edge_index dtype. Reads only the FIRST E 8-byte words,
// in-bounds whether the buffer holds 2E int32 or 2E int64.
// ---------------------------------------------------------------------------
__global__ void detect_idx_kernel(const long long* __restrict__ ei,
                                  int N, int E) {
    int stride = gridDim.x * blockDim.x;
    for (int t = blockIdx.x * blockDim.x + threadIdx.x; t < E; t += stride) {
        long long vv = ei[t];
        if (vv < 0 || vv >= (long long)N) { g_idx_is64 = 0; return; }
    }
}

// ---------------------------------------------------------------------------
// Kernel 1: per-node RMSNorm + MLP -> g_phi [N,384]
// 256 threads, TM=64 nodes/CTA, 4x8 register microtile, f32x2 packed FMA.
// ---------------------------------------------------------------------------
__global__ void __launch_bounds__(256)
node_phi_kernel(const float* __restrict__ s,
                const float* __restrict__ w1, const float* __restrict__ bias1,
                const float* __restrict__ w2, const float* __restrict__ bias2,
                const float* __restrict__ rmsw, int N) {
    extern __shared__ float smem[];
    float* sS = smem;                 // TM * SROW
    float* sW = smem + TM * SROW;     // CDIM * SROW

    const int tid = threadIdx.x;
    const int n0 = blockIdx.x * TM;

    // ---- load s tile (coalesced float4) ----
    const float4* S4 = (const float4*)s;
    for (int t = tid; t < TM * (CDIM / 4); t += 256) {
        int m = t >> 5, cq = t & 31;
        float4 val = make_float4(0.f, 0.f, 0.f, 0.f);
        if (n0 + m < N) val = S4[(size_t)(n0 + m) * (CDIM / 4) + cq];
        *(float4*)&sS[m * SROW + cq * 4] = val;
    }
    __syncthreads();

    // ---- RMSNorm: 4 threads per row ----
    {
        int m = tid >> 2, part = tid & 3;
        float ss = 0.f;
        #pragma unroll
        for (int q = 0; q < 8; q++) {
            float4 a = *(float4*)&sS[m * SROW + part * 32 + q * 4];
            ss += a.x * a.x + a.y * a.y + a.z * a.z + a.w * a.w;
        }
        ss += __shfl_xor_sync(0xffffffffu, ss, 1);
        ss += __shfl_xor_sync(0xffffffffu, ss, 2);
        float sc = rsqrtf(ss * (1.0f / CDIM) + EPS_F);
        #pragma unroll
        for (int q = 0; q < 8; q++) {
            int c = part * 32 + q * 4;
            float4 a = *(float4*)&sS[m * SROW + c];
            float4 w = *(const float4*)&rmsw[c];
            a.x *= sc * w.x; a.y *= sc * w.y; a.z *= sc * w.z; a.w *= sc * w.w;
            *(float4*)&sS[m * SROW + c] = a;
        }
    }

    // ---- stage W1 into shared ----
    const float4* W1_4 = (const float4*)w1;
    for (int t = tid; t < CDIM * (CDIM / 4); t += 256) {
        int r = t >> 5, cq = t & 31;
        *(float4*)&sW[r * SROW + cq * 4] = W1_4[r * (CDIM / 4) + cq];
    }
    __syncthreads();

    const int tc = tid & 15;   // 16 col-lanes; d = tc + 16*j
    const int tr = tid >> 4;   // 16 row-groups; m = tr*4 + i

    // ---- Stage 1: H = silu(Snorm @ W1^T + b1), f32x2 accumulation ----
    unsigned long long acc[4][8];
    #pragma unroll
    for (int i = 0; i < 4; i++)
        #pragma unroll
        for (int j = 0; j < 8; j++) acc[i][j] = 0ull;

    #pragma unroll 2
    for (int c = 0; c < CDIM; c += 4) {
        unsigned long long au0[4], au1[4], bu0[8], bu1[8];
        #pragma unroll
        for (int i = 0; i < 4; i++)
            lds_v2u64(au0[i], au1[i], &sS[(tr * 4 + i) * SROW + c]);
        #pragma unroll
        for (int j = 0; j < 8; j++)
            lds_v2u64(bu0[j], bu1[j], &sW[(tc + 16 * j) * SROW + c]);
        #pragma unroll
        for (int i = 0; i < 4; i++)
            #pragma unroll
            for (int j = 0; j < 8; j++) {
                acc[i][j] = ffma2(au0[i], bu0[j], acc[i][j]);
                acc[i][j] = ffma2(au1[i], bu1[j], acc[i][j]);
            }
    }
    // bias + silu (in registers)
    float hreg[4][8];
    #pragma unroll
    for (int j = 0; j < 8; j++) {
        float bb = bias1[tc + 16 * j];
        #pragma unroll
        for (int i = 0; i < 4; i++) {
            float x = unpack_sum(acc[i][j]) + bb;
            hreg[i][j] = x / (1.0f + __expf(-x));
        }
    }
    __syncthreads();
    // H overwrites snorm tile
    #pragma unroll
    for (int i = 0; i < 4; i++)
        #pragma unroll
        for (int j = 0; j < 8; j++)
            sS[(tr * 4 + i) * SROW + tc + 16 * j] = hreg[i][j];
    __syncthreads();

    // ---- Stage 2: phi_g = H @ W2_g^T + b2_g  for g = 0..2 ----
    for (int g = 0; g < 3; g++) {
        const float4* W2_4 = (const float4*)(w2 + (size_t)g * CDIM * CDIM);
        for (int t = tid; t < CDIM * (CDIM / 4); t += 256) {
            int r = t >> 5, cq = t & 31;
            *(float4*)&sW[r * SROW + cq * 4] = W2_4[r * (CDIM / 4) + cq];
        }
        __syncthreads();

        unsigned long long pac[4][8];
        #pragma unroll
        for (int i = 0; i < 4; i++)
            #pragma unroll
            for (int j = 0; j < 8; j++) pac[i][j] = 0ull;

        #pragma unroll 2
        for (int c = 0; c < CDIM; c += 4) {
            unsigned long long au0[4], au1[4], bu0[8], bu1[8];
            #pragma unroll
            for (int i = 0; i < 4; i++)
                lds_v2u64(au0[i], au1[i], &sS[(tr * 4 + i) * SROW + c]);
            #pragma unroll
            for (int j = 0; j < 8; j++)
                lds_v2u64(bu0[j], bu1[j], &sW[(tc + 16 * j) * SROW + c]);
            #pragma unroll
            for (int i = 0; i < 4; i++)
                #pragma unroll
                for (int j = 0; j < 8; j++) {
                    pac[i][j] = ffma2(au0[i], bu0[j], pac[i][j]);
                    pac[i][j] = ffma2(au1[i], bu1[j], pac[i][j]);
                }
        }
        #pragma unroll
        for (int i = 0; i < 4; i++) {
            int node = n0 + tr * 4 + i;
            if (node < N) {
                float* dst = &g_phi[(size_t)node * (3 * CDIM) + g * CDIM];
                #pragma unroll
                for (int j = 0; j < 8; j++)
                    dst[tc + 16 * j] = unpack_sum(pac[i][j]) +
                                       bias2[g * CDIM + tc + 16 * j];
            }
        }
        __syncthreads();
    }
}

// ---------------------------------------------------------------------------
// Kernel 2: edge gather-multiply-scatter. One warp per edge, one float4
// column slice per lane. ALL 10 global loads issued up-front (MLP=10);
// rbf streamed with __ldcs (evict-first) so phi/v/out stay L2-resident.
// ---------------------------------------------------------------------------
__global__ void __launch_bounds__(256)
edge_kernel(const void* __restrict__ ei_raw,
            const float* __restrict__ rbf,
            const float* __restrict__ ev,
            const float* __restrict__ v,
            float* __restrict__ out, int N, int E) {
    const int wid = threadIdx.x >> 5;
    const int lane = threadIdx.x & 31;
    const int e = blockIdx.x * 8 + wid;
    if (e >= E) return;

    int di, sj;
    if (g_idx_is64) {
        const long long* ei = (const long long*)ei_raw;
        di = (int)ei[e];          // destination (segment index)
        sj = (int)ei[E + e];      // source
    } else {
        const int* ei = (const int*)ei_raw;
        di = ei[e];
        sj = ei[E + e];
    }
    // clamp defensively (garbage indices must never fault)
    di = min(max(di, 0), N - 1);
    sj = min(max(sj, 0), N - 1);

    const float4* Phi = (const float4*)g_phi;
    const float4* R4  = (const float4*)rbf;
    const float4* V4  = (const float4*)v;

    const size_t pb = (size_t)sj * 96;
    const size_t rb = (size_t)e * 96;

    // ---- issue every load before any use ----
    float4 p0 = Phi[pb + lane];
    float4 p1 = Phi[pb + 32 + lane];
    float4 p2 = Phi[pb + 64 + lane];
    float4 r0 = __ldcs(&R4[rb + lane]);
    float4 r1 = __ldcs(&R4[rb + 32 + lane]);
    float4 r2 = __ldcs(&R4[rb + 64 + lane]);
    float4 v0 = V4[((size_t)sj * 3 + 0) * 32 + lane];
    float4 v1 = V4[((size_t)sj * 3 + 1) * 32 + lane];
    float4 v2 = V4[((size_t)sj * 3 + 2) * 32 + lane];
    float  e0 = __ldg(&ev[(size_t)e * 3 + 0]);
    float  e1 = __ldg(&ev[(size_t)e * 3 + 1]);
    float  e2 = __ldg(&ev[(size_t)e * 3 + 2]);

    float4 ms  = make_float4(p0.x * r0.x * SCALE_F, p0.y * r0.y * SCALE_F,
                             p0.z * r0.z * SCALE_F, p0.w * r0.w * SCALE_F);
    float4 mvv = make_float4(p1.x * r1.x * SCALE_F, p1.y * r1.y * SCALE_F,
                             p1.z * r1.z * SCALE_F, p1.w * r1.w * SCALE_F);
    float4 mvs = make_float4(p2.x * r2.x * SCALE_F, p2.y * r2.y * SCALE_F,
                             p2.z * r2.z * SCALE_F, p2.w * r2.w * SCALE_F);

    float4* OutS = (float4*)out;                            // [N,128]
    float4* OutV = (float4*)(out + (size_t)N * CDIM);       // [N,3,128]

    atomicAdd(&OutS[(size_t)di * 32 + lane], ms);

    float4 d0 = make_float4(fmaf(v0.x, mvv.x, e0 * mvs.x),
                            fmaf(v0.y, mvv.y, e0 * mvs.y),
                            fmaf(v0.z, mvv.z, e0 * mvs.z),
                            fmaf(v0.w, mvv.w, e0 * mvs.w));
    atomicAdd(&OutV[((size_t)di * 3 + 0) * 32 + lane], d0);
    float4 d1 = make_float4(fmaf(v1.x, mvv.x, e1 * mvs.x),
                            fmaf(v1.y, mvv.y, e1 * mvs.y),
                            fmaf(v1.z, mvv.z, e1 * mvs.z),
                            fmaf(v1.w, mvv.w, e1 * mvs.w));
    atomicAdd(&OutV[((size_t)di * 3 + 1) * 32 + lane], d1);
    float4 d2 = make_float4(fmaf(v2.x, mvv.x, e2 * mvs.x),
                            fmaf(v2.y, mvv.y, e2 * mvs.y),
                            fmaf(v2.z, mvv.z, e2 * mvs.z),
                            fmaf(v2.w, mvv.w, e2 * mvs.w));
    atomicAdd(&OutV[((size_t)di * 3 + 2) * 32 + lane], d2);
}

// ---------------------------------------------------------------------------
// Launch
// Input order: s, v, edge_index, rbf_filter, edge_vector, w1, b1, w2, b2,
//              rms_w.   Output: [s_out (N*128) | v_out (N*3*128)] fp32.
// ---------------------------------------------------------------------------
extern "C" void kernel_launch(void* const* d_in, const int* in_sizes, int n_in,
                              void* d_out, int out_size) {
    const float* s    = (const float*)d_in[0];
    const float* v    = (const float*)d_in[1];
    const void*  ei   = d_in[2];
    const float* rbf  = (const float*)d_in[3];
    const float* ev   = (const float*)d_in[4];
    const float* w1   = (const float*)d_in[5];
    const float* b1   = (const float*)d_in[6];
    const float* w2   = (const float*)d_in[7];
    const float* b2   = (const float*)d_in[8];
    const float* rmsw = (const float*)d_in[9];

    const int N = in_sizes[0] / CDIM;       // 10000
    const int E = in_sizes[2] / 2;          // 160000
    float* out = (float*)d_out;

    // Kernel 0: out = [s | v]; reset dtype flag to "int64"
    {
        int n_s4 = N * (CDIM / 4);
        int n_total4 = N * CDIM;            // (N*512 floats)/4
        int blocks = (n_total4 + 255) / 256;
        init_out_kernel<<<blocks, 256>>>((const float4*)s, (const float4*)v,
                                         (float4*)out, n_s4, n_total4);
    }

    // Kernel 0b: probe edge_index dtype (reads only first E 8-byte words)
    detect_idx_kernel<<<160, 256>>>((const long long*)ei, N, E);

    // Kernel 1: phi
    {
        size_t smem_bytes = (size_t)(TM + CDIM) * SROW * sizeof(float); // ~99 KB
        cudaFuncSetAttribute(node_phi_kernel,
                             cudaFuncAttributeMaxDynamicSharedMemorySize,
                             (int)smem_bytes);
        int blocks = (N + TM - 1) / TM;
        node_phi_kernel<<<blocks, 256, smem_bytes>>>(s, w1, b1, w2, b2, rmsw, N);
    }

    // Kernel 2: edges
    {
        int blocks = (E + 7) / 8;
        edge_kernel<<<blocks, 256>>>(ei, rbf, ev, v, out, N, E);
    }
}